// round 3
// baseline (speedup 1.0000x reference)
#include <cuda_runtime.h>
#include <math.h>

#define NB 32
#define NC 1024
#define NM 1024
#define ND 512
#define NR 64

#define CS_SPLIT 32   // c-chunks for p2a (each 32 wide)
#define KS_SPLIT 16   // d-chunks for p2b (each 32 wide)

// ---- device scratch (static: no allocations allowed) ----
__device__ float g_tsum[NB * NC];                 // 128 KB
__device__ float g_WqT[ND * NC];                  // 2 MB
__device__ float g_rsum[NR];
__device__ float g_kpart[CS_SPLIT][NB * ND];      // 2 MB
__device__ float g_vpart[CS_SPLIT][NB * ND];      // 2 MB
__device__ float g_ksum[NB * ND];
__device__ float g_vsum[NB * ND];
__device__ float g_upart[KS_SPLIT][NB * NC];      // 2 MB
__device__ float g_ypart[KS_SPLIT][NB * NC];      // 2 MB
__device__ float g_u[NB * NC];
__device__ float g_y[NB * NC];

__device__ __forceinline__ float warp_sum(float v) {
    #pragma unroll
    for (int o = 16; o; o >>= 1) v += __shfl_down_sync(0xffffffffu, v, o);
    return v;
}

// ---------------------------------------------------------------------------
// k_init: blocks [0,512): tiled transpose of Wq (1024x512) -> WqT (512x1024)
//         blocks [512,520): rsum[r] = sum_m R_full[r, m]
// ---------------------------------------------------------------------------
__global__ __launch_bounds__(256) void k_init(const float* __restrict__ Wq,
                                              const float* __restrict__ Rf) {
    int bx = blockIdx.x;
    int tid = threadIdx.x;
    if (bx < 512) {
        __shared__ float tile[32][33];
        int ct = bx & 31;        // c tile (C/32 = 32)
        int dt = bx >> 5;        // d tile (D/32 = 16)
        int lx = tid & 31;
        int ly = tid >> 5;       // 0..7
        #pragma unroll
        for (int j = 0; j < 4; j++) {
            int cl = ly + 8 * j;
            tile[cl][lx] = Wq[(ct * 32 + cl) * ND + dt * 32 + lx];
        }
        __syncthreads();
        #pragma unroll
        for (int j = 0; j < 4; j++) {
            int dl = ly + 8 * j;
            g_WqT[(dt * 32 + dl) * NC + ct * 32 + lx] = tile[lx][dl];
        }
    } else {
        int r = (bx - 512) * 8 + (tid >> 5);    // 64 rows total
        int lane = tid & 31;
        float acc = 0.f;
        #pragma unroll
        for (int k = 0; k < NM / 32; k++)
            acc += Rf[r * NM + k * 32 + lane];
        acc = warp_sum(acc);
        if (lane == 0) g_rsum[r] = acc;
    }
}

// ---------------------------------------------------------------------------
// k_tsum: tsum[b,c] = sum_m T[b,c,m]   (warp per row, float4 loads)
// grid 4096 x 256 threads
// ---------------------------------------------------------------------------
__global__ __launch_bounds__(256) void k_tsum(const float* __restrict__ T) {
    int row = blockIdx.x * 8 + (threadIdx.x >> 5);   // b*NC + c, 32768 rows
    int lane = threadIdx.x & 31;
    const float4* T4 = reinterpret_cast<const float4*>(T) + (size_t)row * (NM / 4);
    float acc = 0.f;
    #pragma unroll
    for (int k = 0; k < 8; k++) {
        float4 v = T4[k * 32 + lane];
        acc += (v.x + v.y) + (v.z + v.w);
    }
    acc = warp_sum(acc);
    if (lane == 0) g_tsum[row] = acc;
}

// ---------------------------------------------------------------------------
// k_p2a: partial GEMMs  kpart/vpart[cs] = tsum[:, c-chunk] @ Wk/Wv[c-chunk, :]
// grid (ND/128, CS_SPLIT) x 128 threads; thread owns one d, acc[32] over b
// ---------------------------------------------------------------------------
__global__ __launch_bounds__(128) void k_p2a(const float* __restrict__ Wk,
                                             const float* __restrict__ Wv) {
    __shared__ float ts[32][32];
    int d  = blockIdx.x * 128 + threadIdx.x;
    int c0 = blockIdx.y * 32;
    for (int t = threadIdx.x; t < NB * 32; t += 128)
        ts[t >> 5][t & 31] = g_tsum[(t >> 5) * NC + c0 + (t & 31)];
    __syncthreads();

    float aK[NB], aV[NB];
    #pragma unroll
    for (int b = 0; b < NB; b++) { aK[b] = 0.f; aV[b] = 0.f; }

    for (int cc = 0; cc < 32; cc++) {
        int c = c0 + cc;
        float wk = Wk[c * ND + d];
        float wv = Wv[c * ND + d];
        #pragma unroll
        for (int b = 0; b < NB; b++) {
            float tv = ts[b][cc];
            aK[b] = fmaf(tv, wk, aK[b]);
            aV[b] = fmaf(tv, wv, aV[b]);
        }
    }
    #pragma unroll
    for (int b = 0; b < NB; b++) {
        g_kpart[blockIdx.y][b * ND + d] = aK[b];
        g_vpart[blockIdx.y][b * ND + d] = aV[b];
    }
}

// deterministic reduction of the 32 k/v partials
__global__ __launch_bounds__(256) void k_redkv() {
    int j = blockIdx.x * 256 + threadIdx.x;    // < NB*ND = 16384
    float sk = 0.f, sv = 0.f;
    #pragma unroll
    for (int s = 0; s < CS_SPLIT; s++) { sk += g_kpart[s][j]; sv += g_vpart[s][j]; }
    g_ksum[j] = sk;
    g_vsum[j] = sv;
}

// ---------------------------------------------------------------------------
// k_p2b: upart/ypart[ks] = ksum/vsum[:, d-chunk] @ WqT/Wout[d-chunk, :]
// grid (NC/128, KS_SPLIT) x 128 threads
// ---------------------------------------------------------------------------
__global__ __launch_bounds__(128) void k_p2b(const float* __restrict__ Wout) {
    __shared__ float ks[32][32], vs[32][32];
    int c  = blockIdx.x * 128 + threadIdx.x;
    int d0 = blockIdx.y * 32;
    for (int t = threadIdx.x; t < NB * 32; t += 128) {
        int b = t >> 5, dd = t & 31;
        ks[b][dd] = g_ksum[b * ND + d0 + dd];
        vs[b][dd] = g_vsum[b * ND + d0 + dd];
    }
    __syncthreads();

    float aU[NB], aY[NB];
    #pragma unroll
    for (int b = 0; b < NB; b++) { aU[b] = 0.f; aY[b] = 0.f; }

    for (int dd = 0; dd < 32; dd++) {
        int d = d0 + dd;
        float wq = g_WqT[d * NC + c];
        float wo = Wout[d * NC + c];
        #pragma unroll
        for (int b = 0; b < NB; b++) {
            aU[b] = fmaf(ks[b][dd], wq, aU[b]);
            aY[b] = fmaf(vs[b][dd], wo, aY[b]);
        }
    }
    #pragma unroll
    for (int b = 0; b < NB; b++) {
        g_upart[blockIdx.y][b * NC + c] = aU[b];
        g_ypart[blockIdx.y][b * NC + c] = aY[b];
    }
}

__global__ __launch_bounds__(256) void k_reduy() {
    int j = blockIdx.x * 256 + threadIdx.x;    // < NB*NC = 32768
    float su = 0.f, sy = 0.f;
    #pragma unroll
    for (int s = 0; s < KS_SPLIT; s++) { su += g_upart[s][j]; sy += g_ypart[s][j]; }
    g_u[j] = su;
    g_y[j] = sy;
}

// ---------------------------------------------------------------------------
// k_p3: s[b,i] = scale * sum_c u[b,c]*T[b,c,i];  w = softmax-weighted rsum;
//       out[b,c,i] = w[b,i] * y[b,c]
// grid (NM/256, NB) x 256 threads
// ---------------------------------------------------------------------------
__global__ __launch_bounds__(256) void k_p3(const float* __restrict__ T,
                                            float* __restrict__ out) {
    __shared__ float us[NC], ys[NC], rs[NR];
    int b = blockIdx.y;
    int i = blockIdx.x * 256 + threadIdx.x;
    for (int t = threadIdx.x; t < NC; t += 256) {
        us[t] = g_u[b * NC + t];
        ys[t] = g_y[b * NC + t];
    }
    if (threadIdx.x < NR) rs[threadIdx.x] = g_rsum[threadIdx.x];
    __syncthreads();

    const float* Tb = T + (size_t)b * NC * NM + i;
    float s = 0.f;
    #pragma unroll 8
    for (int c = 0; c < NC; c++)
        s = fmaf(us[c], Tb[(size_t)c * NM], s);
    s *= 0.044194173824159216f;   // 1/sqrt(512)

    float mx = -1e30f;
    #pragma unroll
    for (int r = 0; r < NR; r++) mx = fmaxf(mx, s * rs[r]);
    float sp = 0.f, spr = 0.f;
    #pragma unroll
    for (int r = 0; r < NR; r++) {
        float p = __expf(fmaf(s, rs[r], -mx));
        sp += p;
        spr = fmaf(p, rs[r], spr);
    }
    float w = spr / sp;

    float* Ob = out + (size_t)b * NC * NM + i;
    #pragma unroll 8
    for (int c = 0; c < NC; c++)
        Ob[(size_t)c * NM] = w * ys[c];
}

// ---------------------------------------------------------------------------
extern "C" void kernel_launch(void* const* d_in, const int* in_sizes, int n_in,
                              void* d_out, int out_size) {
    const float* T    = (const float*)d_in[0];
    const float* Wq   = (const float*)d_in[1];
    const float* Wk   = (const float*)d_in[2];
    const float* Wv   = (const float*)d_in[3];
    const float* Wout = (const float*)d_in[4];
    const float* Rf   = (const float*)d_in[5];
    float* out = (float*)d_out;

    k_init<<<520, 256>>>(Wq, Rf);
    k_tsum<<<4096, 256>>>(T);
    k_p2a<<<dim3(ND / 128, CS_SPLIT), 128>>>(Wk, Wv);
    k_redkv<<<NB * ND / 256, 256>>>();
    k_p2b<<<dim3(NC / 128, KS_SPLIT), 128>>>(Wout);
    k_reduy<<<NB * NC / 256, 256>>>();
    k_p3<<<dim3(NM / 256, NB), 256>>>(T, out);
}

// round 4
// speedup vs baseline: 1.6776x; 1.6776x over previous
#include <cuda_runtime.h>
#include <math.h>

#define NB 32
#define NC 1024
#define NM 1024
#define ND 512
#define NR 64

#define CS_SPLIT 32   // c-chunks for p2a
#define KS_SPLIT 16   // d-chunks for p2b
#define SCH 16        // c-chunks for k_s (64 c each)

// ---- device scratch (static: no allocations allowed) ----
__device__ float g_tsum[NB * NC];
__device__ float g_WqT[ND * NC];
__device__ float g_rsum[NR];
__device__ float g_kpart[CS_SPLIT][NB * ND];
__device__ float g_vpart[CS_SPLIT][NB * ND];
__device__ float g_ksum[NB * ND];
__device__ float g_vsum[NB * ND];
__device__ float g_upart[KS_SPLIT][NB * NC];
__device__ float g_ypart[KS_SPLIT][NB * NC];
__device__ float g_u[NB * NC];
__device__ float g_y[NB * NC];
__device__ float g_spart[SCH][NB * NM];
__device__ float g_w[NB * NM];

__device__ __forceinline__ float warp_sum(float v) {
    #pragma unroll
    for (int o = 16; o; o >>= 1) v += __shfl_down_sync(0xffffffffu, v, o);
    return v;
}

// ---------------------------------------------------------------------------
// k_init: blocks [0,512): tiled transpose of Wq (1024x512) -> WqT (512x1024)
//         blocks [512,520): rsum[r] = sum_m R_full[r, m]
// ---------------------------------------------------------------------------
__global__ __launch_bounds__(256) void k_init(const float* __restrict__ Wq,
                                              const float* __restrict__ Rf) {
    int bx = blockIdx.x;
    int tid = threadIdx.x;
    if (bx < 512) {
        __shared__ float tile[32][33];
        int ct = bx & 31;
        int dt = bx >> 5;
        int lx = tid & 31;
        int ly = tid >> 5;
        #pragma unroll
        for (int j = 0; j < 4; j++) {
            int cl = ly + 8 * j;
            tile[cl][lx] = Wq[(ct * 32 + cl) * ND + dt * 32 + lx];
        }
        __syncthreads();
        #pragma unroll
        for (int j = 0; j < 4; j++) {
            int dl = ly + 8 * j;
            g_WqT[(dt * 32 + dl) * NC + ct * 32 + lx] = tile[lx][dl];
        }
    } else {
        int r = (bx - 512) * 8 + (tid >> 5);
        int lane = tid & 31;
        float acc = 0.f;
        #pragma unroll
        for (int k = 0; k < NM / 32; k++)
            acc += Rf[r * NM + k * 32 + lane];
        acc = warp_sum(acc);
        if (lane == 0) g_rsum[r] = acc;
    }
}

// ---------------------------------------------------------------------------
// k_tsum: tsum[b,c] = sum_m T[b,c,m]   (warp per row, float4 loads)
// ---------------------------------------------------------------------------
__global__ __launch_bounds__(256) void k_tsum(const float* __restrict__ T) {
    int row = blockIdx.x * 8 + (threadIdx.x >> 5);
    int lane = threadIdx.x & 31;
    const float4* T4 = reinterpret_cast<const float4*>(T) + (size_t)row * (NM / 4);
    float acc = 0.f;
    #pragma unroll
    for (int k = 0; k < 8; k++) {
        float4 v = T4[k * 32 + lane];
        acc += (v.x + v.y) + (v.z + v.w);
    }
    acc = warp_sum(acc);
    if (lane == 0) g_tsum[row] = acc;
}

// ---------------------------------------------------------------------------
// k_p2a: partial GEMMs  kpart/vpart[cs] = tsum[:, c-chunk] @ Wk/Wv[c-chunk, :]
// ---------------------------------------------------------------------------
__global__ __launch_bounds__(128) void k_p2a(const float* __restrict__ Wk,
                                             const float* __restrict__ Wv) {
    __shared__ float ts[32][32];
    int d  = blockIdx.x * 128 + threadIdx.x;
    int c0 = blockIdx.y * 32;
    for (int t = threadIdx.x; t < NB * 32; t += 128)
        ts[t >> 5][t & 31] = g_tsum[(t >> 5) * NC + c0 + (t & 31)];
    __syncthreads();

    float aK[NB], aV[NB];
    #pragma unroll
    for (int b = 0; b < NB; b++) { aK[b] = 0.f; aV[b] = 0.f; }

    for (int cc = 0; cc < 32; cc++) {
        int c = c0 + cc;
        float wk = Wk[c * ND + d];
        float wv = Wv[c * ND + d];
        #pragma unroll
        for (int b = 0; b < NB; b++) {
            float tv = ts[b][cc];
            aK[b] = fmaf(tv, wk, aK[b]);
            aV[b] = fmaf(tv, wv, aV[b]);
        }
    }
    #pragma unroll
    for (int b = 0; b < NB; b++) {
        g_kpart[blockIdx.y][b * ND + d] = aK[b];
        g_vpart[blockIdx.y][b * ND + d] = aV[b];
    }
}

// deterministic float4 reduction of the 32 k/v partials
__global__ __launch_bounds__(256) void k_redkv() {
    int j = blockIdx.x * 256 + threadIdx.x;    // float4 index < NB*ND/4 = 4096
    float4 sk = {0.f, 0.f, 0.f, 0.f}, sv = {0.f, 0.f, 0.f, 0.f};
    #pragma unroll
    for (int s = 0; s < CS_SPLIT; s++) {
        float4 a = reinterpret_cast<const float4*>(g_kpart[s])[j];
        float4 b = reinterpret_cast<const float4*>(g_vpart[s])[j];
        sk.x += a.x; sk.y += a.y; sk.z += a.z; sk.w += a.w;
        sv.x += b.x; sv.y += b.y; sv.z += b.z; sv.w += b.w;
    }
    reinterpret_cast<float4*>(g_ksum)[j] = sk;
    reinterpret_cast<float4*>(g_vsum)[j] = sv;
}

// ---------------------------------------------------------------------------
// k_p2b: upart/ypart[ks] = ksum/vsum[:, d-chunk] @ WqT/Wout[d-chunk, :]
// ---------------------------------------------------------------------------
__global__ __launch_bounds__(128) void k_p2b(const float* __restrict__ Wout) {
    __shared__ float ks[32][32], vs[32][32];
    int c  = blockIdx.x * 128 + threadIdx.x;
    int d0 = blockIdx.y * 32;
    for (int t = threadIdx.x; t < NB * 32; t += 128) {
        int b = t >> 5, dd = t & 31;
        ks[b][dd] = g_ksum[b * ND + d0 + dd];
        vs[b][dd] = g_vsum[b * ND + d0 + dd];
    }
    __syncthreads();

    float aU[NB], aY[NB];
    #pragma unroll
    for (int b = 0; b < NB; b++) { aU[b] = 0.f; aY[b] = 0.f; }

    for (int dd = 0; dd < 32; dd++) {
        int d = d0 + dd;
        float wq = g_WqT[d * NC + c];
        float wo = Wout[d * NC + c];
        #pragma unroll
        for (int b = 0; b < NB; b++) {
            aU[b] = fmaf(ks[b][dd], wq, aU[b]);
            aY[b] = fmaf(vs[b][dd], wo, aY[b]);
        }
    }
    #pragma unroll
    for (int b = 0; b < NB; b++) {
        g_upart[blockIdx.y][b * NC + c] = aU[b];
        g_ypart[blockIdx.y][b * NC + c] = aY[b];
    }
}

__global__ __launch_bounds__(256) void k_reduy() {
    int j = blockIdx.x * 256 + threadIdx.x;    // float4 index < NB*NC/4 = 8192
    float4 su = {0.f, 0.f, 0.f, 0.f}, sy = {0.f, 0.f, 0.f, 0.f};
    #pragma unroll
    for (int s = 0; s < KS_SPLIT; s++) {
        float4 a = reinterpret_cast<const float4*>(g_upart[s])[j];
        float4 b = reinterpret_cast<const float4*>(g_ypart[s])[j];
        su.x += a.x; su.y += a.y; su.z += a.z; su.w += a.w;
        sy.x += b.x; sy.y += b.y; sy.z += b.z; sy.w += b.w;
    }
    reinterpret_cast<float4*>(g_u)[j] = su;
    reinterpret_cast<float4*>(g_y)[j] = sy;
}

// ---------------------------------------------------------------------------
// k_s: partial s: spart[ch][b,i] = sum_{c in chunk} u[b,c]*T[b,c,i]
// grid (SCH, NB) = 512 blocks x 256 threads; thread owns float4 of i.
// ---------------------------------------------------------------------------
__global__ __launch_bounds__(256) void k_s(const float* __restrict__ T) {
    __shared__ float us[NC / SCH];          // 64
    int b  = blockIdx.y;
    int c0 = blockIdx.x * (NC / SCH);
    if (threadIdx.x < NC / SCH)
        us[threadIdx.x] = g_u[b * NC + c0 + threadIdx.x];
    __syncthreads();

    const float4* T4 = reinterpret_cast<const float4*>(T)
                     + (size_t)b * NC * (NM / 4)
                     + (size_t)c0 * (NM / 4) + threadIdx.x;
    float4 acc = {0.f, 0.f, 0.f, 0.f};
    #pragma unroll 8
    for (int cc = 0; cc < NC / SCH; cc++) {
        float4 t = T4[(size_t)cc * (NM / 4)];
        float u = us[cc];
        acc.x = fmaf(u, t.x, acc.x);
        acc.y = fmaf(u, t.y, acc.y);
        acc.z = fmaf(u, t.z, acc.z);
        acc.w = fmaf(u, t.w, acc.w);
    }
    reinterpret_cast<float4*>(g_spart[blockIdx.x] + b * NM)[threadIdx.x] = acc;
}

// ---------------------------------------------------------------------------
// k_w: reduce SCH partials, scale, 64-wide softmax -> w[b,i]
// grid 128 x 256
// ---------------------------------------------------------------------------
__global__ __launch_bounds__(256) void k_w() {
    __shared__ float rs[NR];
    int idx = blockIdx.x * 256 + threadIdx.x;   // b*NM + i, < 32768
    if (threadIdx.x < NR) rs[threadIdx.x] = g_rsum[threadIdx.x];
    __syncthreads();

    float s = 0.f;
    #pragma unroll
    for (int p = 0; p < SCH; p++) s += g_spart[p][idx];
    s *= 0.044194173824159216f;   // 1/sqrt(512)

    float mx = -1e30f;
    #pragma unroll
    for (int r = 0; r < NR; r++) mx = fmaxf(mx, s * rs[r]);
    float sp = 0.f, spr = 0.f;
    #pragma unroll
    for (int r = 0; r < NR; r++) {
        float p = __expf(fmaf(s, rs[r], -mx));
        sp += p;
        spr = fmaf(p, rs[r], spr);
    }
    g_w[idx] = spr / sp;
}

// ---------------------------------------------------------------------------
// k_out: out[b,c,i] = w[b,i] * y[b,c]  — streaming float4 broadcast write
// grid NB*NC/8 = 4096 blocks x 256 threads; block handles 8 rows of one b.
// ---------------------------------------------------------------------------
__global__ __launch_bounds__(256) void k_out(float* __restrict__ out) {
    int base_row = blockIdx.x * 8;              // b*NC + c, 8 rows same b
    int b = base_row >> 10;
    float4 w4 = reinterpret_cast<const float4*>(g_w + b * NM)[threadIdx.x];
    #pragma unroll
    for (int k = 0; k < 8; k++) {
        int row = base_row + k;
        float yv = __ldg(&g_y[row]);
        float4 o;
        o.x = w4.x * yv; o.y = w4.y * yv; o.z = w4.z * yv; o.w = w4.w * yv;
        reinterpret_cast<float4*>(out)[(size_t)row * (NM / 4) + threadIdx.x] = o;
    }
}

// ---------------------------------------------------------------------------
extern "C" void kernel_launch(void* const* d_in, const int* in_sizes, int n_in,
                              void* d_out, int out_size) {
    const float* T    = (const float*)d_in[0];
    const float* Wq   = (const float*)d_in[1];
    const float* Wk   = (const float*)d_in[2];
    const float* Wv   = (const float*)d_in[3];
    const float* Wout = (const float*)d_in[4];
    const float* Rf   = (const float*)d_in[5];
    float* out = (float*)d_out;

    k_init<<<520, 256>>>(Wq, Rf);
    k_tsum<<<4096, 256>>>(T);
    k_p2a<<<dim3(ND / 128, CS_SPLIT), 128>>>(Wk, Wv);
    k_redkv<<<NB * ND / 4 / 256, 256>>>();
    k_p2b<<<dim3(NC / 128, KS_SPLIT), 128>>>(Wout);
    k_reduy<<<NB * NC / 4 / 256, 256>>>();
    k_s<<<dim3(SCH, NB), 256>>>(T);
    k_w<<<NB * NM / 256, 256>>>();
    k_out<<<NB * NC / 8, 256>>>(out);
}

// round 5
// speedup vs baseline: 2.2359x; 1.3327x over previous
#include <cuda_runtime.h>
#include <math.h>

#define NB 32
#define NC 1024
#define NM 1024
#define ND 512
#define NR 64

#define CS_SPLIT 32             // c-chunks for p2a (32 c each)
#define KS_SPLIT 16             // d-chunks for p2b (32 d each)
#define SCH 16                  // c-chunks for k_s (64 c each)
#define D_CH (ND / KS_SPLIT)    // 32
#define C_CH (NC / SCH)         // 64
#define ITILE 128               // i-tile for k_wout

// ---- device scratch (static: no allocations allowed) ----
__device__ float g_tsum[NB * NC];
__device__ float g_rsum[NR];
__device__ float g_kpart[CS_SPLIT][NB * ND];
__device__ float g_vpart[CS_SPLIT][NB * ND];
__device__ float g_upart[KS_SPLIT][NB * NC];
__device__ float g_ypart[KS_SPLIT][NB * NC];
__device__ float g_spart[SCH][NB * NM];

__device__ __forceinline__ float warp_sum(float v) {
    #pragma unroll
    for (int o = 16; o; o >>= 1) v += __shfl_down_sync(0xffffffffu, v, o);
    return v;
}

// ---------------------------------------------------------------------------
// k_tsum: blocks [0,4096): tsum[b,c] = sum_m T[b,c,m]  (warp/row, float4)
//         blocks [4096,4104): rsum[r] = sum_m R_full[r,m]
// ---------------------------------------------------------------------------
__global__ __launch_bounds__(256) void k_tsum(const float* __restrict__ T,
                                              const float* __restrict__ Rf) {
    if (blockIdx.x < 4096) {
        int row = blockIdx.x * 8 + (threadIdx.x >> 5);
        int lane = threadIdx.x & 31;
        const float4* T4 = reinterpret_cast<const float4*>(T) + (size_t)row * (NM / 4);
        float acc = 0.f;
        #pragma unroll
        for (int k = 0; k < 8; k++) {
            float4 v = T4[k * 32 + lane];
            acc += (v.x + v.y) + (v.z + v.w);
        }
        acc = warp_sum(acc);
        if (lane == 0) g_tsum[row] = acc;
    } else {
        int r = (blockIdx.x - 4096) * 8 + (threadIdx.x >> 5);   // 64 rows
        int lane = threadIdx.x & 31;
        float acc = 0.f;
        #pragma unroll
        for (int k = 0; k < NM / 32; k++)
            acc += Rf[r * NM + k * 32 + lane];
        acc = warp_sum(acc);
        if (lane == 0) g_rsum[r] = acc;
    }
}

// ---------------------------------------------------------------------------
// k_p2a: kpart/vpart[cs][b,d] = sum_{c in chunk} tsum[b,c]*Wk/Wv[c,d]
// grid (ND/128, CS_SPLIT) x 128; thread owns d, acc[32] over b.
// ---------------------------------------------------------------------------
__global__ __launch_bounds__(128) void k_p2a(const float* __restrict__ Wk,
                                             const float* __restrict__ Wv) {
    __shared__ float ts[NB][32];
    int d  = blockIdx.x * 128 + threadIdx.x;
    int c0 = blockIdx.y * 32;
    for (int e = threadIdx.x; e < NB * 32; e += 128)
        ts[e >> 5][e & 31] = g_tsum[(e >> 5) * NC + c0 + (e & 31)];
    __syncthreads();

    float aK[NB], aV[NB];
    #pragma unroll
    for (int b = 0; b < NB; b++) { aK[b] = 0.f; aV[b] = 0.f; }

    #pragma unroll 4
    for (int cc = 0; cc < 32; cc++) {
        int c = c0 + cc;
        float wk = Wk[(size_t)c * ND + d];
        float wv = Wv[(size_t)c * ND + d];
        #pragma unroll
        for (int b = 0; b < NB; b++) {
            float tv = ts[b][cc];
            aK[b] = fmaf(tv, wk, aK[b]);
            aV[b] = fmaf(tv, wv, aV[b]);
        }
    }
    #pragma unroll
    for (int b = 0; b < NB; b++) {
        g_kpart[blockIdx.y][b * ND + d] = aK[b];
        g_vpart[blockIdx.y][b * ND + d] = aV[b];
    }
}

// ---------------------------------------------------------------------------
// k_p2b: fuses kv-partial reduction + both GEMMs, no Wq transpose needed.
//   upart[ks][b,c] = sum_{d in chunk} ksum[b,d]*Wq[c,d]
//   ypart[ks][b,c] = sum_{d in chunk} vsum[b,d]*Wout[d,c]
// grid (NC/128, KS_SPLIT) x 128; thread owns c.
// ---------------------------------------------------------------------------
__global__ __launch_bounds__(128) void k_p2b(const float* __restrict__ Wq,
                                             const float* __restrict__ Wout) {
    __shared__ float ks[NB][D_CH], vs[NB][D_CH];
    int c  = blockIdx.x * 128 + threadIdx.x;
    int d0 = blockIdx.y * D_CH;

    // reduce the 32 k/v partials into the smem tile (coalesced, high MLP)
    for (int e = threadIdx.x; e < NB * D_CH; e += 128) {
        int addr = (e >> 5) * ND + d0 + (e & (D_CH - 1));
        float sk = 0.f, sv = 0.f;
        #pragma unroll
        for (int p = 0; p < CS_SPLIT; p++) {
            sk += g_kpart[p][addr];
            sv += g_vpart[p][addr];
        }
        ks[e >> 5][e & (D_CH - 1)] = sk;
        vs[e >> 5][e & (D_CH - 1)] = sv;
    }
    __syncthreads();

    // thread-private Wq row slice (contiguous 128B -> 8x LDG.128, L2-hot)
    float wqr[D_CH];
    {
        const float4* wq4 = reinterpret_cast<const float4*>(Wq + (size_t)c * ND + d0);
        #pragma unroll
        for (int q = 0; q < D_CH / 4; q++) {
            float4 v = wq4[q];
            wqr[q * 4 + 0] = v.x; wqr[q * 4 + 1] = v.y;
            wqr[q * 4 + 2] = v.z; wqr[q * 4 + 3] = v.w;
        }
    }

    float aU[NB], aY[NB];
    #pragma unroll
    for (int b = 0; b < NB; b++) { aU[b] = 0.f; aY[b] = 0.f; }

    #pragma unroll 4
    for (int dd = 0; dd < D_CH; dd++) {
        float wq = wqr[dd];
        float wo = Wout[(size_t)(d0 + dd) * NC + c];   // coalesced
        #pragma unroll
        for (int b = 0; b < NB; b++) {
            aU[b] = fmaf(ks[b][dd], wq, aU[b]);
            aY[b] = fmaf(vs[b][dd], wo, aY[b]);
        }
    }
    #pragma unroll
    for (int b = 0; b < NB; b++) {
        g_upart[blockIdx.y][b * NC + c] = aU[b];
        g_ypart[blockIdx.y][b * NC + c] = aY[b];
    }
}

// ---------------------------------------------------------------------------
// k_s: fuses u-reduction. spart[ch][b,i] = sum_{c in chunk} u[b,c]*T[b,c,i]
// grid (SCH, NB) x 256; thread owns a float4 of i.
// ---------------------------------------------------------------------------
__global__ __launch_bounds__(256) void k_s(const float* __restrict__ T) {
    __shared__ float us[C_CH];
    int b  = blockIdx.y;
    int c0 = blockIdx.x * C_CH;
    if (threadIdx.x < C_CH) {
        float u = 0.f;
        #pragma unroll
        for (int p = 0; p < KS_SPLIT; p++)
            u += g_upart[p][b * NC + c0 + threadIdx.x];
        us[threadIdx.x] = u;
    }
    __syncthreads();

    const float4* T4 = reinterpret_cast<const float4*>(T)
                     + ((size_t)b * NC + c0) * (NM / 4) + threadIdx.x;
    float4 acc = {0.f, 0.f, 0.f, 0.f};
    #pragma unroll 8
    for (int cc = 0; cc < C_CH; cc++) {
        float4 t = T4[(size_t)cc * (NM / 4)];
        float u = us[cc];
        acc.x = fmaf(u, t.x, acc.x);
        acc.y = fmaf(u, t.y, acc.y);
        acc.z = fmaf(u, t.z, acc.z);
        acc.w = fmaf(u, t.w, acc.w);
    }
    reinterpret_cast<float4*>(g_spart[blockIdx.x] + b * NM)[threadIdx.x] = acc;
}

// ---------------------------------------------------------------------------
// k_wout: fuses s-reduction + softmax + y-reduction + output write.
// block = (i-tile of 128, b); grid (NM/ITILE, NB) = 256 blocks x 128 thr.
// Each softmax computed exactly once; EX2 phase overlaps store phase
// across resident blocks.
// ---------------------------------------------------------------------------
__global__ __launch_bounds__(128) void k_wout(float* __restrict__ out) {
    __shared__ __align__(16) float w_s[ITILE];
    __shared__ float y_s[NC];
    __shared__ float rs[NR];
    int b  = blockIdx.y;
    int i0 = blockIdx.x * ITILE;
    int tid = threadIdx.x;

    // phase A: rsum to smem + y reduction (L2-hot, shared across 8 blocks/b)
    if (tid < NR) rs[tid] = g_rsum[tid];
    for (int e = tid; e < NC; e += 128) {
        float y = 0.f;
        #pragma unroll
        for (int p = 0; p < KS_SPLIT; p++)
            y += g_ypart[p][b * NC + e];
        y_s[e] = y;
    }
    __syncthreads();

    // phase B: s reduction + 64-wide softmax -> w (one item per thread)
    {
        int i = i0 + tid;
        float s = 0.f;
        #pragma unroll
        for (int p = 0; p < SCH; p++) s += g_spart[p][b * NM + i];
        s *= 0.044194173824159216f;   // 1/sqrt(512)

        float mx = -1e30f;
        #pragma unroll
        for (int r = 0; r < NR; r++) mx = fmaxf(mx, s * rs[r]);
        float sp = 0.f, spr = 0.f;
        #pragma unroll
        for (int r = 0; r < NR; r++) {
            float p = __expf(fmaf(s, rs[r], -mx));
            sp += p;
            spr = fmaf(p, rs[r], spr);
        }
        w_s[tid] = spr / sp;
    }
    __syncthreads();

    // phase C: out[b,c,i0:i0+128] = w * y[c]; warp writes 512B contiguous/c
    int ci = tid >> 5;                 // 0..3
    int i4 = tid & 31;                 // float4 lane within i-tile
    float4 w4 = reinterpret_cast<const float4*>(w_s)[i4];
    float4* O4 = reinterpret_cast<float4*>(out);
    #pragma unroll 4
    for (int c = ci; c < NC; c += 4) {
        float yv = y_s[c];
        float4 o;
        o.x = w4.x * yv; o.y = w4.y * yv; o.z = w4.z * yv; o.w = w4.w * yv;
        O4[((size_t)(b * NC + c) * NM + i0) / 4 + i4] = o;
    }
}

// ---------------------------------------------------------------------------
extern "C" void kernel_launch(void* const* d_in, const int* in_sizes, int n_in,
                              void* d_out, int out_size) {
    const float* T    = (const float*)d_in[0];
    const float* Wq   = (const float*)d_in[1];
    const float* Wk   = (const float*)d_in[2];
    const float* Wv   = (const float*)d_in[3];
    const float* Wout = (const float*)d_in[4];
    const float* Rf   = (const float*)d_in[5];
    float* out = (float*)d_out;

    k_tsum<<<4104, 256>>>(T, Rf);
    k_p2a<<<dim3(ND / 128, CS_SPLIT), 128>>>(Wk, Wv);
    k_p2b<<<dim3(NC / 128, KS_SPLIT), 128>>>(Wq, Wout);
    k_s<<<dim3(SCH, NB), 256>>>(T);
    k_wout<<<dim3(NM / ITILE, NB), 128>>>(out);
}

// round 7
// speedup vs baseline: 2.3705x; 1.0602x over previous
#include <cuda_runtime.h>
#include <math.h>

#define NB 32
#define NC 1024
#define NM 1024
#define ND 512
#define NR 64

#define CS_SPLIT 32             // c-chunks for p2a (32 c each)
#define KS_SPLIT 16             // d-chunks for p2b (32 d each)
#define SCH 32                  // c-chunks for k_s (32 c each)
#define D_CH (ND / KS_SPLIT)    // 32
#define C_CH (NC / SCH)         // 32
#define ITILE 128               // i-tile for k_wout

// ---- device scratch (static: no allocations allowed) ----
__device__ float g_tsum[NB * NC];
__device__ float g_rsum[NR];
__device__ float g_kpart[CS_SPLIT][NB * ND];
__device__ float g_vpart[CS_SPLIT][NB * ND];
__device__ float g_upart[KS_SPLIT][NB * NC];
__device__ float g_ypart[KS_SPLIT][NB * NC];
__device__ float g_spart[SCH][NB * NM];

__device__ __forceinline__ float warp_sum(float v) {
    #pragma unroll
    for (int o = 16; o; o >>= 1) v += __shfl_down_sync(0xffffffffu, v, o);
    return v;
}

// ---------------------------------------------------------------------------
// k_tsum: blocks [0,4096): tsum[b,c] = sum_m T[b,c,m]  (warp/row, float4,
//         all 8 loads issued before any reduction -> MLP=8)
//         blocks [4096,4104): rsum[r] = sum_m R_full[r,m]
// ---------------------------------------------------------------------------
__global__ __launch_bounds__(256) void k_tsum(const float* __restrict__ T,
                                              const float* __restrict__ Rf) {
    if (blockIdx.x < 4096) {
        int row = blockIdx.x * 8 + (threadIdx.x >> 5);
        int lane = threadIdx.x & 31;
        const float4* T4 = reinterpret_cast<const float4*>(T) + (size_t)row * (NM / 4);
        float4 t[8];
        #pragma unroll
        for (int k = 0; k < 8; k++) t[k] = T4[k * 32 + lane];
        float acc = 0.f;
        #pragma unroll
        for (int k = 0; k < 8; k++)
            acc += (t[k].x + t[k].y) + (t[k].z + t[k].w);
        acc = warp_sum(acc);
        if (lane == 0) g_tsum[row] = acc;
    } else {
        int r = (blockIdx.x - 4096) * 8 + (threadIdx.x >> 5);   // 64 rows
        int lane = threadIdx.x & 31;
        const float4* R4 = reinterpret_cast<const float4*>(Rf) + (size_t)r * (NM / 4);
        float4 t[8];
        #pragma unroll
        for (int k = 0; k < 8; k++) t[k] = R4[k * 32 + lane];
        float acc = 0.f;
        #pragma unroll
        for (int k = 0; k < 8; k++)
            acc += (t[k].x + t[k].y) + (t[k].z + t[k].w);
        acc = warp_sum(acc);
        if (lane == 0) g_rsum[r] = acc;
    }
}

// ---------------------------------------------------------------------------
// k_p2a: kpart/vpart[cs][b,d] = sum_{c in chunk} tsum[b,c]*Wk/Wv[c,d]
// grid (ND/128, CS_SPLIT) x 128; thread owns d, acc[32] over b.
// ---------------------------------------------------------------------------
__global__ __launch_bounds__(128) void k_p2a(const float* __restrict__ Wk,
                                             const float* __restrict__ Wv) {
    __shared__ float ts[NB][32];
    int d  = blockIdx.x * 128 + threadIdx.x;
    int c0 = blockIdx.y * 32;
    for (int e = threadIdx.x; e < NB * 32; e += 128)
        ts[e >> 5][e & 31] = g_tsum[(e >> 5) * NC + c0 + (e & 31)];
    __syncthreads();

    float aK[NB], aV[NB];
    #pragma unroll
    for (int b = 0; b < NB; b++) { aK[b] = 0.f; aV[b] = 0.f; }

    #pragma unroll 4
    for (int cc = 0; cc < 32; cc++) {
        int c = c0 + cc;
        float wk = Wk[(size_t)c * ND + d];
        float wv = Wv[(size_t)c * ND + d];
        #pragma unroll
        for (int b = 0; b < NB; b++) {
            float tv = ts[b][cc];
            aK[b] = fmaf(tv, wk, aK[b]);
            aV[b] = fmaf(tv, wv, aV[b]);
        }
    }
    #pragma unroll
    for (int b = 0; b < NB; b++) {
        g_kpart[blockIdx.y][b * ND + d] = aK[b];
        g_vpart[blockIdx.y][b * ND + d] = aV[b];
    }
}

// ---------------------------------------------------------------------------
// k_p2b: fuses kv-partial reduction + both GEMMs (no Wq transpose).
//   upart[ks][b,c] = sum_{d in chunk} ksum[b,d]*Wq[c,d]
//   ypart[ks][b,c] = sum_{d in chunk} vsum[b,d]*Wout[d,c]
// grid (NC/128, KS_SPLIT) x 128; thread owns c.
// ---------------------------------------------------------------------------
__global__ __launch_bounds__(128) void k_p2b(const float* __restrict__ Wq,
                                             const float* __restrict__ Wout) {
    __shared__ float ks[NB][D_CH], vs[NB][D_CH];
    int c  = blockIdx.x * 128 + threadIdx.x;
    int d0 = blockIdx.y * D_CH;

    for (int e = threadIdx.x; e < NB * D_CH; e += 128) {
        int addr = (e >> 5) * ND + d0 + (e & (D_CH - 1));
        float sk = 0.f, sv = 0.f;
        #pragma unroll
        for (int p = 0; p < CS_SPLIT; p++) {
            sk += g_kpart[p][addr];
            sv += g_vpart[p][addr];
        }
        ks[e >> 5][e & (D_CH - 1)] = sk;
        vs[e >> 5][e & (D_CH - 1)] = sv;
    }
    __syncthreads();

    float wqr[D_CH];
    {
        const float4* wq4 = reinterpret_cast<const float4*>(Wq + (size_t)c * ND + d0);
        #pragma unroll
        for (int q = 0; q < D_CH / 4; q++) {
            float4 v = wq4[q];
            wqr[q * 4 + 0] = v.x; wqr[q * 4 + 1] = v.y;
            wqr[q * 4 + 2] = v.z; wqr[q * 4 + 3] = v.w;
        }
    }

    float aU[NB], aY[NB];
    #pragma unroll
    for (int b = 0; b < NB; b++) { aU[b] = 0.f; aY[b] = 0.f; }

    #pragma unroll 4
    for (int dd = 0; dd < D_CH; dd++) {
        float wq = wqr[dd];
        float wo = Wout[(size_t)(d0 + dd) * NC + c];
        #pragma unroll
        for (int b = 0; b < NB; b++) {
            aU[b] = fmaf(ks[b][dd], wq, aU[b]);
            aY[b] = fmaf(vs[b][dd], wo, aY[b]);
        }
    }
    #pragma unroll
    for (int b = 0; b < NB; b++) {
        g_upart[blockIdx.y][b * NC + c] = aU[b];
        g_ypart[blockIdx.y][b * NC + c] = aY[b];
    }
}

// ---------------------------------------------------------------------------
// k_s: fuses u-reduction. spart[ch][b,i] = sum_{c in chunk} u[b,c]*T[b,c,i]
// grid (SCH, NB) = 1024 blocks x 256; thread owns one float4 of i.
// Loads batched 8-deep before FMAs -> MLP_eff ~8.
// ---------------------------------------------------------------------------
__global__ __launch_bounds__(256) void k_s(const float* __restrict__ T) {
    __shared__ float us[C_CH];
    int b  = blockIdx.y;
    int c0 = blockIdx.x * C_CH;
    if (threadIdx.x < C_CH) {
        float u = 0.f;
        #pragma unroll
        for (int p = 0; p < KS_SPLIT; p++)
            u += g_upart[p][b * NC + c0 + threadIdx.x];
        us[threadIdx.x] = u;
    }
    __syncthreads();

    const float4* T4 = reinterpret_cast<const float4*>(T)
                     + ((size_t)b * NC + c0) * (NM / 4) + threadIdx.x;
    float4 acc = {0.f, 0.f, 0.f, 0.f};
    #pragma unroll
    for (int cc = 0; cc < C_CH; cc += 8) {
        float4 t[8];
        #pragma unroll
        for (int j = 0; j < 8; j++)
            t[j] = T4[(size_t)(cc + j) * (NM / 4)];
        #pragma unroll
        for (int j = 0; j < 8; j++) {
            float u = us[cc + j];
            acc.x = fmaf(u, t[j].x, acc.x);
            acc.y = fmaf(u, t[j].y, acc.y);
            acc.z = fmaf(u, t[j].z, acc.z);
            acc.w = fmaf(u, t[j].w, acc.w);
        }
    }
    reinterpret_cast<float4*>(g_spart[blockIdx.x] + b * NM)[threadIdx.x] = acc;
}

// ---------------------------------------------------------------------------
// k_wout: fuses s-reduction + softmax + y-reduction + output write.
// grid (NM/ITILE, NB) = 256 blocks x 256 threads.
// ---------------------------------------------------------------------------
__global__ __launch_bounds__(256) void k_wout(float* __restrict__ out) {
    __shared__ __align__(16) float w_s[ITILE];
    __shared__ float y_s[NC];
    __shared__ float rs[NR];
    int b  = blockIdx.y;
    int i0 = blockIdx.x * ITILE;
    int tid = threadIdx.x;

    // phase A: rsum to smem + y reduction
    if (tid < NR) rs[tid] = g_rsum[tid];
    for (int e = tid; e < NC; e += 256) {
        float y = 0.f;
        #pragma unroll
        for (int p = 0; p < KS_SPLIT; p++)
            y += g_ypart[p][b * NC + e];
        y_s[e] = y;
    }
    __syncthreads();

    // phase B: s reduction + 64-wide softmax -> w (threads < ITILE)
    if (tid < ITILE) {
        int i = i0 + tid;
        float s = 0.f;
        #pragma unroll
        for (int p = 0; p < SCH; p++) s += g_spart[p][b * NM + i];
        s *= 0.044194173824159216f;   // 1/sqrt(512)

        float mx = -1e30f;
        #pragma unroll
        for (int r = 0; r < NR; r++) mx = fmaxf(mx, s * rs[r]);
        float sp = 0.f, spr = 0.f;
        #pragma unroll
        for (int r = 0; r < NR; r++) {
            float p = __expf(fmaf(s, rs[r], -mx));
            sp += p;
            spr = fmaf(p, rs[r], spr);
        }
        w_s[tid] = spr / sp;
    }
    __syncthreads();

    // phase C: out[b,c,i0:i0+128] = w * y[c]; 8 c's x 32 float4-lanes per pass
    int ci = tid >> 5;                 // 0..7
    int i4 = tid & 31;                 // float4 lane within i-tile
    float4 w4 = reinterpret_cast<const float4*>(w_s)[i4];
    float4* O4 = reinterpret_cast<float4*>(out);
    #pragma unroll 4
    for (int c = ci; c < NC; c += 8) {
        float yv = y_s[c];
        float4 o;
        o.x = w4.x * yv; o.y = w4.y * yv; o.z = w4.z * yv; o.w = w4.w * yv;
        O4[((size_t)(b * NC + c) * NM + i0) / 4 + i4] = o;
    }
}

// ---------------------------------------------------------------------------
extern "C" void kernel_launch(void* const* d_in, const int* in_sizes, int n_in,
                              void* d_out, int out_size) {
    const float* T    = (const float*)d_in[0];
    const float* Wq   = (const float*)d_in[1];
    const float* Wk   = (const float*)d_in[2];
    const float* Wv   = (const float*)d_in[3];
    const float* Wout = (const float*)d_in[4];
    const float* Rf   = (const float*)d_in[5];
    float* out = (float*)d_out;

    k_tsum<<<4104, 256>>>(T, Rf);
    k_p2a<<<dim3(ND / 128, CS_SPLIT), 128>>>(Wk, Wv);
    k_p2b<<<dim3(NC / 128, KS_SPLIT), 128>>>(Wq, Wout);
    k_s<<<dim3(SCH, NB), 256>>>(T);
    k_wout<<<dim3(NM / ITILE, NB), 256>>>(out);
}